// round 1
// baseline (speedup 1.0000x reference)
#include <cuda_runtime.h>

// Problem shape (fixed for this dataset): N=500000, K=81 neighbors, C=4, OUT=8.
#define KNB 81
#define OUTC 8
#define TPB  64
#define CAP  1000000   // static capacity for padded points scratch

// Scratch (device globals: allocation-free rule)
__device__ float4 g_pts4[CAP];
__device__ int    g_is64;

// ---------- helpers ----------
__device__ __forceinline__ unsigned long long pack2(float a, float b) {
    unsigned long long r;
    asm("mov.b64 %0, {%1, %2};" : "=l"(r) : "f"(a), "f"(b));
    return r;
}
__device__ __forceinline__ void fma2(unsigned long long& acc,
                                     unsigned long long a, unsigned long long b) {
    // packed fp32x2 FMA (Blackwell): acc = a*b + acc  (elementwise on 2 lanes)
    asm("fma.rn.f32x2 %0, %1, %2, %0;" : "+l"(acc) : "l"(a), "l"(b));
}

// ---------- kernel 0: detect index dtype (int64 vs int32) ----------
// If the buffer really is int64, every 8-byte element is < N.
// If it is int32 data, an 8-byte read combines two random int32 < N, so the
// high word is nonzero with prob ~1 - 1/N per element; 4 checks => robust.
__global__ void detect_idx_dtype(const unsigned long long* __restrict__ idx, int N) {
    if (threadIdx.x == 0 && blockIdx.x == 0) {
        int is64 = 1;
        #pragma unroll
        for (int e = 1; e <= 4; e++)
            if (idx[e] >= (unsigned long long)N) is64 = 0;
        g_is64 = is64;
    }
}

// ---------- kernel 1: pad points to float4 with |p|^2 in .w ----------
__global__ void pad_points(const float* __restrict__ pts, int N) {
    int i = blockIdx.x * blockDim.x + threadIdx.x;
    if (i < N) {
        float x = pts[3 * i], y = pts[3 * i + 1], z = pts[3 * i + 2];
        g_pts4[i] = make_float4(x, y, z, x * x + y * y + z * z);
    }
}

// ---------- kernel 2: main fused gather + conv ----------
__global__ __launch_bounds__(TPB) void conv_main(
    const void* __restrict__ indices_raw,
    const float* __restrict__ dw,       // [81][4]
    const float* __restrict__ weight,   // [4][81][8]
    const float* __restrict__ bias,     // [8]
    float* __restrict__ out,            // [N][8]
    int N)
{
    __shared__ int sIdx[TPB * KNB];                    // 20736 B
    __shared__ unsigned long long sW[KNB * 16];        // 10368 B: [j][c*4 + lpair]

    const int tid = threadIdx.x;

    // Build packed weight table: W[j,c,l] = dw[j,c] * weight[c,j,l], pairs over l.
    for (int e = tid; e < KNB * 16; e += TPB) {
        int j = e >> 4, r = e & 15, c = r >> 2, lp = r & 3;
        float dv = dw[j * 4 + c];
        const float* wp = weight + ((c * KNB + j) * OUTC + 2 * lp);
        sW[e] = pack2(dv * wp[0], dv * wp[1]);
    }

    // Stage this block's index rows (contiguous region) into shared as int32.
    const int b0 = blockIdx.x * TPB;
    const int npts = min(TPB, N - b0);
    const int nelem = npts * KNB;
    if (g_is64) {
        const ulonglong2* src =
            (const ulonglong2*)((const long long*)indices_raw + (long long)b0 * KNB);
        int nvec = nelem >> 1;
        for (int e = tid; e < nvec; e += TPB) {
            ulonglong2 v = src[e];
            *(int2*)&sIdx[2 * e] = make_int2((int)v.x, (int)v.y);
        }
        if ((nelem & 1) && tid == 0)
            sIdx[nelem - 1] = (int)((const long long*)src)[nelem - 1];
    } else {
        const int4* src = (const int4*)((const int*)indices_raw + (long long)b0 * KNB);
        int nvec = nelem >> 2;
        for (int e = tid; e < nvec; e += TPB)
            *(int4*)&sIdx[4 * e] = src[e];
        for (int e = (nvec << 2) + tid; e < nelem; e += TPB)
            sIdx[e] = ((const int*)src)[e];
    }
    __syncthreads();

    const int n = b0 + tid;
    if (n >= N) return;
    const int* myIdx = &sIdx[tid * KNB];   // stride 81 ints -> conflict-free LDS

    // Self neighbor (indices[n,0]); dist_j = |p|^2 - 2 p.s + |s|^2 + 1
    float4 s = g_pts4[myIdx[0]];
    const float c0 = s.w + 1.0f;
    const float msx = -2.0f * s.x, msy = -2.0f * s.y, msz = -2.0f * s.z;

    unsigned long long acc[4];
    #pragma unroll
    for (int lp = 0; lp < 4; lp++) acc[lp] = pack2(bias[2 * lp], bias[2 * lp + 1]);

    #pragma unroll 3
    for (int j = 0; j < KNB; j++) {
        float4 p = g_pts4[myIdx[j]];       // 1 LDG.128 = 1 sector (random)
        float d = p.w + c0;
        d = fmaf(msx, p.x, d);
        d = fmaf(msy, p.y, d);
        d = fmaf(msz, p.z, d);

        unsigned long long f[4];
        f[0] = pack2(p.x, p.x);
        f[1] = pack2(p.y, p.y);
        f[2] = pack2(p.z, p.z);
        f[3] = pack2(d,   d);

        const ulonglong2* wrow = (const ulonglong2*)&sW[j * 16];  // broadcast LDS.128
        #pragma unroll
        for (int c = 0; c < 4; c++) {
            ulonglong2 wa = wrow[c * 2];
            ulonglong2 wb = wrow[c * 2 + 1];
            fma2(acc[0], f[c], wa.x);
            fma2(acc[1], f[c], wa.y);
            fma2(acc[2], f[c], wb.x);
            fma2(acc[3], f[c], wb.y);
        }
    }

    // 8 outputs = 2 x STG.128, 32B-aligned, coalesced across the warp.
    float2 o0 = *(float2*)&acc[0], o1 = *(float2*)&acc[1];
    float2 o2 = *(float2*)&acc[2], o3 = *(float2*)&acc[3];
    float4* op = (float4*)(out + (long long)n * OUTC);
    op[0] = make_float4(o0.x, o0.y, o1.x, o1.y);
    op[1] = make_float4(o2.x, o2.y, o3.x, o3.y);
}

// ---------- launcher ----------
extern "C" void kernel_launch(void* const* d_in, const int* in_sizes, int n_in,
                              void* d_out, int out_size) {
    const float* points  = (const float*)d_in[0];   // [N,3]
    const void*  indices = d_in[1];                 // [N,81] int64 (or int32, detected)
    const float* dw      = (const float*)d_in[2];   // [81,4]
    const float* weight  = (const float*)d_in[3];   // [4,81,8]
    const float* bias    = (const float*)d_in[4];   // [8]
    float* out = (float*)d_out;

    const int N = in_sizes[0] / 3;

    detect_idx_dtype<<<1, 32>>>((const unsigned long long*)indices, N);
    pad_points<<<(N + 255) / 256, 256>>>(points, N);
    conv_main<<<(N + TPB - 1) / TPB, TPB>>>(indices, dw, weight, bias, out, N);
}

// round 2
// speedup vs baseline: 1.0346x; 1.0346x over previous
#include <cuda_runtime.h>

// Problem shape (fixed): N=500000, K=81 neighbors, C=4, OUT=8.
#define KNB 81
#define OUTC 8
#define TPB  128
#define BATCH 9
#define CAP  1000000   // static capacity for padded points scratch

// Scratch (device global: allocation-free rule)
__device__ float4 g_pts4[CAP];

// ---------- helpers ----------
__device__ __forceinline__ unsigned long long pack2(float a, float b) {
    unsigned long long r;
    asm("mov.b64 %0, {%1, %2};" : "=l"(r) : "f"(a), "f"(b));
    return r;
}
__device__ __forceinline__ void fma2(unsigned long long& acc,
                                     unsigned long long a, unsigned long long b) {
    // packed fp32x2 FMA (Blackwell): acc = a*b + acc
    asm("fma.rn.f32x2 %0, %1, %2, %0;" : "+l"(acc) : "l"(a), "l"(b));
}

// ---------- kernel 1: pad points to float4 with |p|^2 in .w ----------
__global__ void pad_points(const float* __restrict__ pts, int N) {
    int i = blockIdx.x * blockDim.x + threadIdx.x;
    if (i < N) {
        float x = pts[3 * i], y = pts[3 * i + 1], z = pts[3 * i + 2];
        g_pts4[i] = make_float4(x, y, z, x * x + y * y + z * z);
    }
}

// ---------- kernel 2: fused gather + conv ----------
__global__ __launch_bounds__(TPB) void conv_main(
    const void* __restrict__ indices_raw,
    const float* __restrict__ dw,       // [81][4]
    const float* __restrict__ weight,   // [4][81][8]
    const float* __restrict__ bias,     // [8]
    float* __restrict__ out,            // [N][8]
    int N)
{
    __shared__ int sIdx[TPB * KNB];                 // 41472 B
    __shared__ unsigned long long sW[KNB * 16];     // 10368 B: [j][c*4 + lpair]

    const int tid = threadIdx.x;

    // Inline dtype detection (uniform across grid; values L2-cached).
    // int64 data: all elements < N. int32 data reinterpreted as u64: high
    // word is a random index, nonzero w.p. ~1-1/N per element.
    const unsigned long long* iq = (const unsigned long long*)indices_raw;
    bool is64 = (iq[1] < (unsigned long long)N) & (iq[2] < (unsigned long long)N)
              & (iq[3] < (unsigned long long)N) & (iq[4] < (unsigned long long)N);

    // Packed weight table: W[j,c,l] = dw[j,c] * weight[c,j,l], pairs over l.
    for (int e = tid; e < KNB * 16; e += TPB) {
        int j = e >> 4, r = e & 15, c = r >> 2, lp = r & 3;
        float dv = dw[j * 4 + c];
        const float* wp = weight + ((c * KNB + j) * OUTC + 2 * lp);
        sW[e] = pack2(dv * wp[0], dv * wp[1]);
    }

    // Stage this block's contiguous index rows into shared as int32 (coalesced).
    const int b0 = blockIdx.x * TPB;
    const int npts = min(TPB, N - b0);
    const int nelem = npts * KNB;
    if (is64) {
        const ulonglong2* src =
            (const ulonglong2*)((const long long*)indices_raw + (long long)b0 * KNB);
        int nvec = nelem >> 1;
        for (int e = tid; e < nvec; e += TPB) {
            ulonglong2 v = src[e];
            *(int2*)&sIdx[2 * e] = make_int2((int)v.x, (int)v.y);
        }
        if ((nelem & 1) && tid == 0)
            sIdx[nelem - 1] = (int)((const long long*)src)[nelem - 1];
    } else {
        const int4* src = (const int4*)((const int*)indices_raw + (long long)b0 * KNB);
        int nvec = nelem >> 2;
        for (int e = tid; e < nvec; e += TPB)
            *(int4*)&sIdx[4 * e] = src[e];
        for (int e = (nvec << 2) + tid; e < nelem; e += TPB)
            sIdx[e] = ((const int*)src)[e];
    }
    __syncthreads();

    const int n = b0 + tid;
    if (n >= N) return;
    const int* myIdx = &sIdx[tid * KNB];   // stride-81 -> conflict-free LDS

    // Self neighbor: dist_j = |p|^2 - 2 p.s + (|s|^2 + 1)
    float4 s = g_pts4[myIdx[0]];
    const float c0 = s.w + 1.0f;
    const float msx = -2.0f * s.x, msy = -2.0f * s.y, msz = -2.0f * s.z;

    unsigned long long acc[4];
    #pragma unroll
    for (int lp = 0; lp < 4; lp++) acc[lp] = pack2(bias[2 * lp], bias[2 * lp + 1]);

    // 81 = 9 batches of 9: prefetch 9 indices, issue 9 independent gathers
    // (MLP=9), then compute. Gathers hit L2 (~250cyc); 9-deep per thread x
    // 16 warps/SM hides it.
    #pragma unroll
    for (int b = 0; b < KNB / BATCH; b++) {
        int   ibuf[BATCH];
        float4 pbuf[BATCH];
        #pragma unroll
        for (int u = 0; u < BATCH; u++) ibuf[u] = myIdx[b * BATCH + u];
        #pragma unroll
        for (int u = 0; u < BATCH; u++) pbuf[u] = g_pts4[ibuf[u]];

        #pragma unroll
        for (int u = 0; u < BATCH; u++) {
            const int j = b * BATCH + u;
            float4 p = pbuf[u];
            float d = p.w + c0;
            d = fmaf(msx, p.x, d);
            d = fmaf(msy, p.y, d);
            d = fmaf(msz, p.z, d);

            unsigned long long f[4];
            f[0] = pack2(p.x, p.x);
            f[1] = pack2(p.y, p.y);
            f[2] = pack2(p.z, p.z);
            f[3] = pack2(d,   d);

            const ulonglong2* wrow = (const ulonglong2*)&sW[j * 16];  // broadcast
            #pragma unroll
            for (int c = 0; c < 4; c++) {
                ulonglong2 wa = wrow[c * 2];
                ulonglong2 wb = wrow[c * 2 + 1];
                fma2(acc[0], f[c], wa.x);
                fma2(acc[1], f[c], wa.y);
                fma2(acc[2], f[c], wb.x);
                fma2(acc[3], f[c], wb.y);
            }
        }
    }

    // 8 outputs = 2 x STG.128, coalesced.
    float2 o0 = *(float2*)&acc[0], o1 = *(float2*)&acc[1];
    float2 o2 = *(float2*)&acc[2], o3 = *(float2*)&acc[3];
    float4* op = (float4*)(out + (long long)n * OUTC);
    op[0] = make_float4(o0.x, o0.y, o1.x, o1.y);
    op[1] = make_float4(o2.x, o2.y, o3.x, o3.y);
}

// ---------- launcher ----------
extern "C" void kernel_launch(void* const* d_in, const int* in_sizes, int n_in,
                              void* d_out, int out_size) {
    const float* points  = (const float*)d_in[0];   // [N,3]
    const void*  indices = d_in[1];                 // [N,81] int64 or int32
    const float* dw      = (const float*)d_in[2];   // [81,4]
    const float* weight  = (const float*)d_in[3];   // [4,81,8]
    const float* bias    = (const float*)d_in[4];   // [8]
    float* out = (float*)d_out;

    const int N = in_sizes[0] / 3;

    pad_points<<<(N + 255) / 256, 256>>>(points, N);
    conv_main<<<(N + TPB - 1) / TPB, TPB>>>(indices, dw, weight, bias, out, N);
}

// round 3
// speedup vs baseline: 1.4741x; 1.4248x over previous
#include <cuda_runtime.h>

// Problem shape (fixed): N=500000, K=81 neighbors, C=4, OUT=8.
#define KNB 81
#define CHUNK 27
#define NCHUNK 3
#define OUTC 8
#define TPB  128
#define BATCH 9
#define CAP  1000000

// Scratch (device global: allocation-free rule)
__device__ float4 g_pts4[CAP];

// ---------- helpers ----------
__device__ __forceinline__ unsigned long long pack2(float a, float b) {
    unsigned long long r;
    asm("mov.b64 %0, {%1, %2};" : "=l"(r) : "f"(a), "f"(b));
    return r;
}
__device__ __forceinline__ void fma2(unsigned long long& acc,
                                     unsigned long long a, unsigned long long b) {
    asm("fma.rn.f32x2 %0, %1, %2, %0;" : "+l"(acc) : "l"(a), "l"(b));
}

// ---------- kernel 1: pad points to float4 with |p|^2 in .w ----------
__global__ void pad_points(const float* __restrict__ pts, int N) {
    int i = blockIdx.x * blockDim.x + threadIdx.x;
    if (i < N) {
        float x = pts[3 * i], y = pts[3 * i + 1], z = pts[3 * i + 2];
        g_pts4[i] = make_float4(x, y, z, x * x + y * y + z * z);
    }
}

// ---------- kernel 2: fused gather + conv ----------
__global__ __launch_bounds__(TPB, 6) void conv_main(
    const void* __restrict__ indices_raw,
    const float* __restrict__ dw,       // [81][4]
    const float* __restrict__ weight,   // [4][81][8]
    const float* __restrict__ bias,     // [8]
    float* __restrict__ out,            // [N][8]
    int N)
{
    __shared__ int sIdx[TPB * CHUNK];               // 13824 B
    __shared__ unsigned long long sW[KNB * 16];     // 10368 B: [j][c*4 + lpair]

    const int tid = threadIdx.x;

    // Inline dtype detection (uniform; L2-cached).
    const unsigned long long* iq = (const unsigned long long*)indices_raw;
    bool is64 = (iq[1] < (unsigned long long)N) & (iq[2] < (unsigned long long)N)
              & (iq[3] < (unsigned long long)N) & (iq[4] < (unsigned long long)N);

    // Packed weight table: W[j,c,l] = dw[j,c] * weight[c,j,l], pairs over l.
    for (int e = tid; e < KNB * 16; e += TPB) {
        int j = e >> 4, r = e & 15, c = r >> 2, lp = r & 3;
        float dv = dw[j * 4 + c];
        const float* wp = weight + ((c * KNB + j) * OUTC + 2 * lp);
        sW[e] = pack2(dv * wp[0], dv * wp[1]);
    }

    const int b0 = blockIdx.x * TPB;
    const int npts = min(TPB, N - b0);
    const int n = b0 + tid;
    const bool active = (n < N);

    // Persistent across chunks:
    float c0 = 0.f, msx = 0.f, msy = 0.f, msz = 0.f;
    unsigned long long acc[4];
    #pragma unroll
    for (int lp = 0; lp < 4; lp++) acc[lp] = pack2(bias[2 * lp], bias[2 * lp + 1]);

    for (int ch = 0; ch < NCHUNK; ch++) {
        __syncthreads();   // protect sIdx reuse
        // Stage chunk: for each local point p, elements [ch*27, ch*27+27) of its row.
        const int nelem = npts * CHUNK;
        if (is64) {
            const long long* src = (const long long*)indices_raw;
            for (int e = tid; e < nelem; e += TPB) {
                int p = e / CHUNK, j = e - p * CHUNK;
                sIdx[e] = (int)src[(long long)(b0 + p) * KNB + ch * CHUNK + j];
            }
        } else {
            const int* src = (const int*)indices_raw;
            for (int e = tid; e < nelem; e += TPB) {
                int p = e / CHUNK, j = e - p * CHUNK;
                sIdx[e] = src[(long long)(b0 + p) * KNB + ch * CHUNK + j];
            }
        }
        __syncthreads();

        if (active) {
            const int* myIdx = &sIdx[tid * CHUNK];
            if (ch == 0) {
                float4 s = g_pts4[myIdx[0]];
                c0 = s.w + 1.0f;
                msx = -2.0f * s.x; msy = -2.0f * s.y; msz = -2.0f * s.z;
            }
            #pragma unroll
            for (int b = 0; b < CHUNK / BATCH; b++) {
                int    ibuf[BATCH];
                float4 pbuf[BATCH];
                #pragma unroll
                for (int u = 0; u < BATCH; u++) ibuf[u] = myIdx[b * BATCH + u];
                #pragma unroll
                for (int u = 0; u < BATCH; u++) pbuf[u] = g_pts4[ibuf[u]];

                #pragma unroll
                for (int u = 0; u < BATCH; u++) {
                    const int j = ch * CHUNK + b * BATCH + u;
                    float4 p = pbuf[u];
                    float d = p.w + c0;
                    d = fmaf(msx, p.x, d);
                    d = fmaf(msy, p.y, d);
                    d = fmaf(msz, p.z, d);

                    unsigned long long f[4];
                    f[0] = pack2(p.x, p.x);
                    f[1] = pack2(p.y, p.y);
                    f[2] = pack2(p.z, p.z);
                    f[3] = pack2(d,   d);

                    const ulonglong2* wrow = (const ulonglong2*)&sW[j * 16];
                    #pragma unroll
                    for (int c = 0; c < 4; c++) {
                        ulonglong2 wa = wrow[c * 2];
                        ulonglong2 wb = wrow[c * 2 + 1];
                        fma2(acc[0], f[c], wa.x);
                        fma2(acc[1], f[c], wa.y);
                        fma2(acc[2], f[c], wb.x);
                        fma2(acc[3], f[c], wb.y);
                    }
                }
            }
        }
    }

    if (active) {
        float2 o0 = *(float2*)&acc[0], o1 = *(float2*)&acc[1];
        float2 o2 = *(float2*)&acc[2], o3 = *(float2*)&acc[3];
        float4* op = (float4*)(out + (long long)n * OUTC);
        op[0] = make_float4(o0.x, o0.y, o1.x, o1.y);
        op[1] = make_float4(o2.x, o2.y, o3.x, o3.y);
    }
}

// ---------- launcher ----------
extern "C" void kernel_launch(void* const* d_in, const int* in_sizes, int n_in,
                              void* d_out, int out_size) {
    const float* points  = (const float*)d_in[0];   // [N,3]
    const void*  indices = d_in[1];                 // [N,81] int64 or int32
    const float* dw      = (const float*)d_in[2];   // [81,4]
    const float* weight  = (const float*)d_in[3];   // [4,81,8]
    const float* bias    = (const float*)d_in[4];   // [8]
    float* out = (float*)d_out;

    const int N = in_sizes[0] / 3;

    pad_points<<<(N + 255) / 256, 256>>>(points, N);
    conv_main<<<(N + TPB - 1) / TPB, TPB>>>(indices, dw, weight, bias, out, N);
}